// round 11
// baseline (speedup 1.0000x reference)
#include <cuda_runtime.h>
#include <cuda_fp16.h>
#include <cstdint>

// LightGCN encoder: fixed-stride slot-allocated adjacency + fp16-stored
// propagation buffers (fp32 accumulate). Warp-per-node layers (zero degree
// divergence, 4x TLP vs 8-lane groups). Layers 1-2 full graph; layer 3 fused
// into the batch gather. D = 64 (one half2 per lane).
// kernel_launch performs ONLY kernel launches (graph-capture rules).
#define D 64
#define SLOTS 80   // fixed adjacency slots per node (max degree << 80)

static constexpr int MAX_NODES = 150016;

// Scratch (no cudaMalloc allowed). fp16 node buffers: hx (=x), h1, h2.
__device__ __half g_hb[3][(size_t)MAX_NODES * D];
__device__ int   g_cursor[MAX_NODES];                   // becomes degree after fill
__device__ uint2 g_adj[(size_t)MAX_NODES * SLOTS];      // packed (src, fp32 w bits)

// ---------------------------------------------------------------------------
// prep: zero cursors AND convert x -> fp16 buffer 0 (independent work fused)
// ---------------------------------------------------------------------------
__global__ void lgcn_prep(const float* __restrict__ ue, const float* __restrict__ ie,
                          int n_users, int n_nodes) {
    int t = blockIdx.x * blockDim.x + threadIdx.x;
    if (t < n_nodes) {
        g_cursor[t] = 0;
        return;
    }
    int i = t - n_nodes;                      // float4 index over node rows
    int total = n_nodes * (D / 4);
    if (i >= total) return;
    int u_lim = n_users * (D / 4);
    float4 v = (i < u_lim) ? reinterpret_cast<const float4*>(ue)[i]
                           : reinterpret_cast<const float4*>(ie)[i - u_lim];
    __half2 p0 = __floats2half2_rn(v.x, v.y);
    __half2 p1 = __floats2half2_rn(v.z, v.w);
    uint2 o = make_uint2(*reinterpret_cast<unsigned*>(&p0), *reinterpret_cast<unsigned*>(&p1));
    reinterpret_cast<uint2*>(g_hb[0])[i] = o;
}

// ---------------------------------------------------------------------------
// fill: self-allocating adjacency. pos = cursor[dst]++ ; slot = dst*SLOTS+pos.
// cursor[n] ends as degree(n). 1 edge/thread (MLP variants regressed).
// ---------------------------------------------------------------------------
__global__ void csr_fill(const int* __restrict__ src, const int* __restrict__ dst,
                         const float* __restrict__ w, int E) {
    int e = blockIdx.x * blockDim.x + threadIdx.x;
    if (e >= E) return;
    int d = __ldg(dst + e);
    int pos = atomicAdd(&g_cursor[d], 1);
    if (pos < SLOTS)
        g_adj[(size_t)d * SLOTS + pos] =
            make_uint2((unsigned)__ldg(src + e), __float_as_uint(__ldg(w + e)));
}

// ---------------------------------------------------------------------------
// layer: ONE WARP per node; lane owns one half2 (4B) of the 128B row:
//   out[n] = Σ_{j < deg(n)} w_j * in[src_j]   (fp32 accumulate, fp16 store)
// All lanes share the degree loop -> zero intra-warp divergence.
// ---------------------------------------------------------------------------
__global__ void lgcn_layer(int in_sel, int out_sel, int n_nodes) {
    int t = blockIdx.x * blockDim.x + threadIdx.x;
    int node = t >> 5;
    if (node >= n_nodes) return;
    unsigned lane = t & 31;

    // half2-unit view of the node table, offset by this lane's column
    const unsigned* __restrict__ hin =
        reinterpret_cast<const unsigned*>(g_hb[in_sel]) + lane;

    int deg = __ldg(&g_cursor[node]);
    if (deg > SLOTS) deg = SLOTS;
    const uint2* __restrict__ adj = g_adj + (size_t)node * SLOTS;

    float sx = 0.f, sy = 0.f;
    int p = 0;
    for (; p + 4 <= deg; p += 4) {
        uint2 m0 = __ldg(adj + p);
        uint2 m1 = __ldg(adj + p + 1);
        uint2 m2 = __ldg(adj + p + 2);
        uint2 m3 = __ldg(adj + p + 3);
        unsigned v0 = __ldg(hin + m0.x * 32u);
        unsigned v1 = __ldg(hin + m1.x * 32u);
        unsigned v2 = __ldg(hin + m2.x * 32u);
        unsigned v3 = __ldg(hin + m3.x * 32u);
        float2 f0 = __half22float2(*reinterpret_cast<const __half2*>(&v0));
        float2 f1 = __half22float2(*reinterpret_cast<const __half2*>(&v1));
        float2 f2 = __half22float2(*reinterpret_cast<const __half2*>(&v2));
        float2 f3 = __half22float2(*reinterpret_cast<const __half2*>(&v3));
        float w0 = __uint_as_float(m0.y), w1 = __uint_as_float(m1.y);
        float w2 = __uint_as_float(m2.y), w3 = __uint_as_float(m3.y);
        sx += w0 * f0.x + w1 * f1.x + w2 * f2.x + w3 * f3.x;
        sy += w0 * f0.y + w1 * f1.y + w2 * f2.y + w3 * f3.y;
    }
    for (; p < deg; ++p) {
        uint2 m = __ldg(adj + p);
        unsigned v = __ldg(hin + m.x * 32u);
        float2 f = __half22float2(*reinterpret_cast<const __half2*>(&v));
        float w = __uint_as_float(m.y);
        sx += w * f.x;
        sy += w * f.y;
    }

    __half2 q = __floats2half2_rn(sx, sy);
    reinterpret_cast<unsigned*>(g_hb[out_sel])[(size_t)node * 32 + lane] =
        *reinterpret_cast<unsigned*>(&q);
}

// ---------------------------------------------------------------------------
// gather + fused layer 3 (only batch rows need h3): ONE WARP per output row;
// lane owns one half2 column (2 floats of the 64-float row):
//   out[r] = 0.25*( x[node] + h1[node] + h2[node] + Σ_j w_j*h2[src_j] )
// ---------------------------------------------------------------------------
__global__ void lgcn_gather(const float* __restrict__ ue, const float* __restrict__ ie,
                            const int* __restrict__ uid, const int* __restrict__ iid,
                            int batch, int n_users, float* __restrict__ out) {
    int t = blockIdx.x * blockDim.x + threadIdx.x;
    int r = t >> 5;                 // output row in [0, 2*batch)
    if (r >= 2 * batch) return;
    unsigned lane = t & 31;

    int node;
    const float* xrow;
    if (r < batch) {
        int u = __ldg(uid + r);
        node = u;
        xrow = ue + (size_t)u * D;
    } else {
        int i = __ldg(iid + (r - batch));
        node = n_users + i;
        xrow = ie + (size_t)i * D;
    }

    // start with x (fp32, exact): lane's 2 floats
    float2 x = reinterpret_cast<const float2*>(xrow)[lane];
    float sx = x.x, sy = x.y;

    // + h1 + h2 at node
    const unsigned* __restrict__ h1 =
        reinterpret_cast<const unsigned*>(g_hb[1]) + lane;
    const unsigned* __restrict__ h2 =
        reinterpret_cast<const unsigned*>(g_hb[2]) + lane;
    {
        unsigned a = __ldg(h1 + (size_t)node * 32u);
        unsigned b = __ldg(h2 + (size_t)node * 32u);
        float2 fa = __half22float2(*reinterpret_cast<const __half2*>(&a));
        float2 fb = __half22float2(*reinterpret_cast<const __half2*>(&b));
        sx += fa.x + fb.x;
        sy += fa.y + fb.y;
    }

    // + fused layer 3: Σ w * h2[src]
    int deg = __ldg(&g_cursor[node]);
    if (deg > SLOTS) deg = SLOTS;
    const uint2* __restrict__ adj = g_adj + (size_t)node * SLOTS;
    int p = 0;
    for (; p + 4 <= deg; p += 4) {
        uint2 m0 = __ldg(adj + p);
        uint2 m1 = __ldg(adj + p + 1);
        uint2 m2 = __ldg(adj + p + 2);
        uint2 m3 = __ldg(adj + p + 3);
        unsigned v0 = __ldg(h2 + m0.x * 32u);
        unsigned v1 = __ldg(h2 + m1.x * 32u);
        unsigned v2 = __ldg(h2 + m2.x * 32u);
        unsigned v3 = __ldg(h2 + m3.x * 32u);
        float2 f0 = __half22float2(*reinterpret_cast<const __half2*>(&v0));
        float2 f1 = __half22float2(*reinterpret_cast<const __half2*>(&v1));
        float2 f2 = __half22float2(*reinterpret_cast<const __half2*>(&v2));
        float2 f3 = __half22float2(*reinterpret_cast<const __half2*>(&v3));
        float w0 = __uint_as_float(m0.y), w1 = __uint_as_float(m1.y);
        float w2 = __uint_as_float(m2.y), w3 = __uint_as_float(m3.y);
        sx += w0 * f0.x + w1 * f1.x + w2 * f2.x + w3 * f3.x;
        sy += w0 * f0.y + w1 * f1.y + w2 * f2.y + w3 * f3.y;
    }
    for (; p < deg; ++p) {
        uint2 m = __ldg(adj + p);
        unsigned v = __ldg(h2 + m.x * 32u);
        float2 f = __half22float2(*reinterpret_cast<const __half2*>(&v));
        float w = __uint_as_float(m.y);
        sx += w * f.x;
        sy += w * f.y;
    }

    const float sc = 0.25f;  // 1 / (NUM_LAYERS + 1)
    float2 o = make_float2(sc * sx, sc * sy);
    reinterpret_cast<float2*>(out + (size_t)r * D)[lane] = o;
}

// ---------------------------------------------------------------------------
extern "C" void kernel_launch(void* const* d_in, const int* in_sizes, int n_in,
                              void* d_out, int out_size) {
    const float* ue  = (const float*)d_in[0];   // [n_users, 64]
    const float* ie  = (const float*)d_in[1];   // [n_items, 64]
    const float* ew  = (const float*)d_in[2];   // [E]
    const int*   eix = (const int*)d_in[3];     // [2, E] (int32)
    const int*   uid = (const int*)d_in[4];     // [B]
    const int*   iid = (const int*)d_in[5];     // [B]
    float* out = (float*)d_out;

    const int n_users = in_sizes[0] / D;
    const int n_items = in_sizes[1] / D;
    const int n_nodes = n_users + n_items;
    const int E       = in_sizes[2];
    const int batch   = in_sizes[4];

    const int* src = eix;
    const int* dst = eix + E;

    const int TB = 256;
    const int prep_threads = n_nodes + n_nodes * (D / 4);
    const int prep_blocks  = (prep_threads + TB - 1) / TB;
    const int edge_blocks  = (E + TB - 1) / TB;
    const long long layer_threads = (long long)n_nodes * 32;
    const int layer_blocks = (int)((layer_threads + TB - 1) / TB);

    // ---- prep: zero cursors + convert x to fp16 (fused) ----
    lgcn_prep<<<prep_blocks, TB>>>(ue, ie, n_users, n_nodes);

    // ---- adjacency fill (self-allocating slots; cursor ends as degree) ----
    csr_fill<<<edge_blocks, TB>>>(src, dst, ew, E);

    // ---- layers 1-2 full graph on fp16 buffers (warp per node) ----
    lgcn_layer<<<layer_blocks, TB>>>(0, 1, n_nodes);
    lgcn_layer<<<layer_blocks, TB>>>(1, 2, n_nodes);

    // ---- gather with fused layer 3 (warp per output row) ----
    const long long gthreads = (long long)2 * batch * 32;
    lgcn_gather<<<(int)((gthreads + TB - 1) / TB), TB>>>(ue, ie, uid, iid,
                                                         batch, n_users, out);
}